// round 17
// baseline (speedup 1.0000x reference)
#include <cuda_runtime.h>
#include <cuda_bf16.h>
#include <cstdint>

#define Dc 128
#define TE 64          // tile for pq/node kernels (256 threads)
#define TEE 32         // tile for edge kernel (256 threads, 8 warps)
#define NN 50000
#define EE 500000
#define MAXT 10.0f
#define XPAD 136   // bf16 per row: 272B stride -> conflict-free ldmatrix
#define EPAD 132   // fp32 ef tile row stride

// Scratch (device globals: no allocation allowed)
__device__ float g_agg[(size_t)NN * Dc];
__device__ float g_csum[(size_t)NN * 3];
__device__ float g_deg[NN];
__device__ float g_P[(size_t)NN * Dc];   // h @ We1[0:128]
__device__ float g_Q[(size_t)NN * Dc];   // h @ We1[128:256]
// Weight fragments: 56 kk-chunks x 16 ntiles x 32 lanes x 16B (hi0,hi1,lo0,lo1)
__device__ uint4 g_wfrag[56 * 16 * 32];

__device__ __forceinline__ float sigmoidf_(float x) { return 1.f / (1.f + __expf(-x)); }
__device__ __forceinline__ float siluf_(float x) { return x / (1.f + __expf(-x)); }
__device__ __forceinline__ float clampt_(float x) { return fminf(fmaxf(x, -MAXT), MAXT); }

__device__ __forceinline__ unsigned pkb(__nv_bfloat16 a, __nv_bfloat16 b) {
    __nv_bfloat162 t(a, b);
    return *(unsigned*)&t;
}
__device__ __forceinline__ void splitbf(float x, __nv_bfloat16& h, __nv_bfloat16& l) {
    h = __float2bfloat16_rn(x);
    l = __float2bfloat16_rn(x - __bfloat162float(h));
}
// vector reduction: one REDG for four adjacent floats (sm_90+)
__device__ __forceinline__ void red4(float* p, float4 v) {
    asm volatile("red.global.add.v4.f32 [%0], {%1, %2, %3, %4};"
                 :: "l"(p), "f"(v.x), "f"(v.y), "f"(v.z), "f"(v.w) : "memory");
}

__device__ __forceinline__ void mma16816(float c[4], const unsigned a[4], unsigned b0, unsigned b1) {
    asm volatile(
        "mma.sync.aligned.m16n8k16.row.col.f32.bf16.bf16.f32 "
        "{%0,%1,%2,%3}, {%4,%5,%6,%7}, {%8,%9}, {%0,%1,%2,%3};"
        : "+f"(c[0]), "+f"(c[1]), "+f"(c[2]), "+f"(c[3])
        : "r"(a[0]), "r"(a[1]), "r"(a[2]), "r"(a[3]), "r"(b0), "r"(b1));
}
__device__ __forceinline__ void ldsm4(unsigned r[4], const void* p) {
    uint32_t sa = (uint32_t)__cvta_generic_to_shared(p);
    asm volatile("ldmatrix.sync.aligned.m8n8.x4.shared.b16 {%0,%1,%2,%3}, [%4];"
                 : "=r"(r[0]), "=r"(r[1]), "=r"(r[2]), "=r"(r[3]) : "r"(sa));
}

__global__ void zero_kernel() {
    const int total = NN * Dc + NN * 3 + NN;
    for (int i = blockIdx.x * blockDim.x + threadIdx.x; i < total; i += gridDim.x * blockDim.x) {
        if (i < NN * Dc) g_agg[i] = 0.f;
        else if (i < NN * Dc + NN * 3) g_csum[i - NN * Dc] = 0.f;
        else g_deg[i - NN * Dc - NN * 3] = 0.f;
    }
}

// Pre-split weights into bf16 hi/lo, fragment-major layout.
// kk chunks: We1 rows0-255 -> 0..15 | We2 -> 16..23 | Wc1 -> 24..31 | Wn1 -> 32..47 | Wn2 -> 48..55
__global__ void prep_weights(const float* __restrict__ We1, const float* __restrict__ We2,
                             const float* __restrict__ Wc1, const float* __restrict__ Wn1,
                             const float* __restrict__ Wn2) {
    int idx = blockIdx.x * blockDim.x + threadIdx.x;
    if (idx >= 56 * 16 * 32) return;
    int lane = idx & 31;
    int f = idx >> 5;
    int kk_t = f >> 4;
    int nn_g = f & 15;
    const float* W; int kk;
    if (kk_t < 16)      { W = We1; kk = kk_t; }
    else if (kk_t < 24) { W = We2; kk = kk_t - 16; }
    else if (kk_t < 32) { W = Wc1; kk = kk_t - 24; }
    else if (kk_t < 48) { W = Wn1; kk = kk_t - 32; }
    else                { W = Wn2; kk = kk_t - 48; }
    int n  = nn_g * 8 + (lane >> 2);
    int k0 = kk * 16 + (lane & 3) * 2;
    float v0 = W[(size_t)(k0 + 0) * Dc + n];
    float v1 = W[(size_t)(k0 + 1) * Dc + n];
    float v2 = W[(size_t)(k0 + 8) * Dc + n];
    float v3 = W[(size_t)(k0 + 9) * Dc + n];
    __nv_bfloat16 h0, l0, h1, l1, h2, l2, h3, l3;
    splitbf(v0, h0, l0); splitbf(v1, h1, l1); splitbf(v2, h2, l2); splitbf(v3, h3, l3);
    g_wfrag[f * 32 + lane] = make_uint4(pkb(h0, h1), pkb(h2, h3), pkb(l0, l1), pkb(l2, l3));
}

// Wide pass (pq/node kernels): warp covers 16 rows x 64 cols, c[8][4]
__device__ __forceinline__ void gemm_pass8(float c[8][4],
                                           const __nv_bfloat16 (*Xh)[XPAD],
                                           const __nv_bfloat16 (*Xl)[XPAD],
                                           int wbase, int rt, int ct, int lane) {
    const int arow = rt * 16 + (lane & 15);
    const int acol8 = (lane & 16) >> 1;
#pragma unroll 1
    for (int kk = 0; kk < 8; kk++) {
        unsigned ah[4], al[4];
        ldsm4(ah, &Xh[arow][kk * 16 + acol8]);
        ldsm4(al, &Xl[arow][kk * 16 + acol8]);
        const uint4* wp = &g_wfrag[((size_t)(wbase + kk) * 16 + ct * 8) * 32 + lane];
#pragma unroll
        for (int nn = 0; nn < 8; nn++) {
            uint4 w = __ldg(wp + nn * 32);
            mma16816(c[nn], ah, w.x, w.y);
            mma16816(c[nn], ah, w.z, w.w);
            mma16816(c[nn], al, w.x, w.y);
        }
    }
}

// Narrow pass (edge kernel, split A): warp covers 16 rows x 32 cols, c[4][4]
__device__ __forceinline__ void gemm_pass4(float c[4][4],
                                           const __nv_bfloat16 (*Xh)[XPAD],
                                           const __nv_bfloat16 (*Xl)[XPAD],
                                           int wbase, int rt, int ct4, int lane) {
    const int arow = rt * 16 + (lane & 15);
    const int acol8 = (lane & 16) >> 1;
#pragma unroll 1
    for (int kk = 0; kk < 8; kk++) {
        unsigned ah[4], al[4];
        ldsm4(ah, &Xh[arow][kk * 16 + acol8]);
        ldsm4(al, &Xl[arow][kk * 16 + acol8]);
        const uint4* wp = &g_wfrag[((size_t)(wbase + kk) * 16 + ct4 * 4) * 32 + lane];
#pragma unroll
        for (int nn = 0; nn < 4; nn++) {
            uint4 w = __ldg(wp + nn * 32);
            mma16816(c[nn], ah, w.x, w.y);
            mma16816(c[nn], ah, w.z, w.w);
            mma16816(c[nn], al, w.x, w.y);
        }
    }
}

// Hi-only-A narrow pass (coord MLP): A lo term dropped (error ~2^-9 on a ~1e-3
// magnitude coord update -> ~1e-6 on coord_out; invisible at 1e-3 tolerance)
__device__ __forceinline__ void gemm_pass4h(float c[4][4],
                                            const __nv_bfloat16 (*Xh)[XPAD],
                                            int wbase, int rt, int ct4, int lane) {
    const int arow = rt * 16 + (lane & 15);
    const int acol8 = (lane & 16) >> 1;
#pragma unroll 1
    for (int kk = 0; kk < 8; kk++) {
        unsigned ah[4];
        ldsm4(ah, &Xh[arow][kk * 16 + acol8]);
        const uint4* wp = &g_wfrag[((size_t)(wbase + kk) * 16 + ct4 * 4) * 32 + lane];
#pragma unroll
        for (int nn = 0; nn < 4; nn++) {
            uint4 w = __ldg(wp + nn * 32);
            mma16816(c[nn], ah, w.x, w.y);
            mma16816(c[nn], ah, w.z, w.w);
        }
    }
}

// P = h @ We1_top, Q = h @ We1_bot
__global__ void __launch_bounds__(256) pq_kernel(const float* __restrict__ h) {
    __shared__ __nv_bfloat16 Xh[TE][XPAD];
    __shared__ __nv_bfloat16 Xl[TE][XPAD];
    const int tid = threadIdx.x;
    const int lane = tid & 31;
    const int warp = tid >> 5;
    const int rt = warp >> 1;
    const int ct = warp & 1;
    const int g = lane >> 2;
    const int tig = lane & 3;
    const int row0 = rt * 16 + g;
    const int base = blockIdx.x * TE;

    for (int i = tid; i < TE * 32; i += 256) {
        int n = base + (i >> 5);
        if (n >= NN) n = NN - 1;
        int l4 = (i & 31) * 4;
        float4 v = __ldg((const float4*)&h[(size_t)n * Dc + l4]);
        __nv_bfloat16 h0, l0, h1, l1, h2, l2, h3, l3;
        splitbf(v.x, h0, l0); splitbf(v.y, h1, l1); splitbf(v.z, h2, l2); splitbf(v.w, h3, l3);
        *(uint2*)&Xh[i >> 5][l4] = make_uint2(pkb(h0, h1), pkb(h2, h3));
        *(uint2*)&Xl[i >> 5][l4] = make_uint2(pkb(l0, l1), pkb(l2, l3));
    }
    __syncthreads();

    float c[8][4];
    const int n0 = base + row0, n1 = base + row0 + 8;
#pragma unroll
    for (int nn = 0; nn < 8; nn++)
#pragma unroll
        for (int j = 0; j < 4; j++) c[nn][j] = 0.f;
    gemm_pass8(c, Xh, Xl, 0, rt, ct, lane);     // We1 top
#pragma unroll
    for (int nn = 0; nn < 8; nn++) {
        int col = ct * 64 + nn * 8 + tig * 2;
        if (n0 < NN) *(float2*)&g_P[(size_t)n0 * Dc + col] = make_float2(c[nn][0], c[nn][1]);
        if (n1 < NN) *(float2*)&g_P[(size_t)n1 * Dc + col] = make_float2(c[nn][2], c[nn][3]);
        c[nn][0] = c[nn][1] = c[nn][2] = c[nn][3] = 0.f;
    }
    gemm_pass8(c, Xh, Xl, 8, rt, ct, lane);     // We1 bottom
#pragma unroll
    for (int nn = 0; nn < 8; nn++) {
        int col = ct * 64 + nn * 8 + tig * 2;
        if (n0 < NN) *(float2*)&g_Q[(size_t)n0 * Dc + col] = make_float2(c[nn][0], c[nn][1]);
        if (n1 < NN) *(float2*)&g_Q[(size_t)n1 * Dc + col] = make_float2(c[nn][2], c[nn][3]);
    }
}

// 8 warps: rt = warp>>2 (16-edge half), ct4 = warp&3 (32-col quarter)
__global__ void __launch_bounds__(256, 4) edge_kernel(
    const int* __restrict__ ei, const float* __restrict__ coord,
    const float* __restrict__ We1, const float* __restrict__ be1,
    const float* __restrict__ be2, const float* __restrict__ Watt, const float* __restrict__ batt,
    const float* __restrict__ bc1, const float* __restrict__ Wc2,
    float* __restrict__ edge_out) {
    __shared__ __nv_bfloat16 Xh[TEE][XPAD];
    __shared__ __nv_bfloat16 Xl[TEE][XPAD];
    __shared__ float sEf[TEE][EPAD];
    __shared__ int sRow[TEE];
    __shared__ int sCol[TEE];
    __shared__ float sRad[TEE];
    __shared__ float sCd[TEE][3];
    __shared__ float sPart[4][TEE];

    const int tid = threadIdx.x;
    const int lane = tid & 31;
    const int warp = tid >> 5;
    const int rt = warp >> 2;            // 0..1: 16-edge row tile
    const int ct4 = warp & 3;            // 0..3: 32-col quarter
    const int g = lane >> 2;
    const int tig = lane & 3;
    const int row0 = rt * 16 + g;
    const int base = blockIdx.x * TEE;

    if (tid < TEE) {
        int ee = base + tid;
        if (ee >= EE) ee = EE - 1;  // clamp; writes masked later
        int r = ei[ee];
        int c = ei[EE + ee];
        sRow[tid] = r;
        sCol[tid] = c;
        float dx = coord[r * 3 + 0] - coord[c * 3 + 0];
        float dy = coord[r * 3 + 1] - coord[c * 3 + 1];
        float dz = coord[r * 3 + 2] - coord[c * 3 + 2];
        sCd[tid][0] = dx; sCd[tid][1] = dy; sCd[tid][2] = dz;
        sRad[tid] = dx * dx + dy * dy + dz * dz;
    }
    __syncthreads();

    // ---- layer1 fused: e1 = silu(P[row] + Q[col] + rad*We1[256] + be1); split-stage ----
    for (int i = tid; i < TEE * 32; i += 256) {
        int e = i >> 5, l4 = (i & 31) * 4;
        float4 p = __ldg((const float4*)&g_P[(size_t)sRow[e] * Dc + l4]);
        float4 q = __ldg((const float4*)&g_Q[(size_t)sCol[e] * Dc + l4]);
        float4 wr = __ldg((const float4*)&We1[(size_t)256 * Dc + l4]);
        float4 b1 = __ldg((const float4*)&be1[l4]);
        float rad = sRad[e];
        float v0 = siluf_(p.x + q.x + rad * wr.x + b1.x);
        float v1 = siluf_(p.y + q.y + rad * wr.y + b1.y);
        float v2 = siluf_(p.z + q.z + rad * wr.z + b1.z);
        float v3 = siluf_(p.w + q.w + rad * wr.w + b1.w);
        __nv_bfloat16 h0, l0, h1, l1, h2, l2, h3, l3;
        splitbf(v0, h0, l0); splitbf(v1, h1, l1); splitbf(v2, h2, l2); splitbf(v3, h3, l3);
        *(uint2*)&Xh[e][l4] = make_uint2(pkb(h0, h1), pkb(h2, h3));
        *(uint2*)&Xl[e][l4] = make_uint2(pkb(l0, l1), pkb(l2, l3));
    }
    __syncthreads();

    // ---- layer2: e2 = silu(e1@We2+be2); att; ef = e2*att ----
    float c[4][4];
#pragma unroll
    for (int nn = 0; nn < 4; nn++)
#pragma unroll
        for (int j = 0; j < 4; j++) c[nn][j] = 0.f;
    gemm_pass4(c, Xh, Xl, 16, rt, ct4, lane);

    {
        float pA = 0.f, pB = 0.f;
#pragma unroll
        for (int nn = 0; nn < 4; nn++) {
            int col = ct4 * 32 + nn * 8 + tig * 2;
            float2 b2 = __ldg((const float2*)&be2[col]);
            float2 wa = __ldg((const float2*)&Watt[col]);
            c[nn][0] = siluf_(c[nn][0] + b2.x);
            c[nn][1] = siluf_(c[nn][1] + b2.y);
            c[nn][2] = siluf_(c[nn][2] + b2.x);
            c[nn][3] = siluf_(c[nn][3] + b2.y);
            pA += c[nn][0] * wa.x + c[nn][1] * wa.y;
            pB += c[nn][2] * wa.x + c[nn][3] * wa.y;
        }
        pA += __shfl_xor_sync(0xffffffffu, pA, 1); pA += __shfl_xor_sync(0xffffffffu, pA, 2);
        pB += __shfl_xor_sync(0xffffffffu, pB, 1); pB += __shfl_xor_sync(0xffffffffu, pB, 2);
        if (tig == 0) { sPart[ct4][row0] = pA; sPart[ct4][row0 + 8] = pB; }
    }
    __syncthreads();
    {
        float ba = __ldg(batt);
        float attA = sigmoidf_(sPart[0][row0] + sPart[1][row0] + sPart[2][row0] + sPart[3][row0] + ba);
        float attB = sigmoidf_(sPart[0][row0 + 8] + sPart[1][row0 + 8] + sPart[2][row0 + 8] + sPart[3][row0 + 8] + ba);
#pragma unroll
        for (int nn = 0; nn < 4; nn++) {
            c[nn][0] *= attA; c[nn][1] *= attA;
            c[nn][2] *= attB; c[nn][3] *= attB;
        }
    }
    __syncthreads();

    // ---- stage ef: fp32 -> sEf (for coalesced store + red.v4), bf16 hi -> Xh (coord A) ----
#pragma unroll
    for (int nn = 0; nn < 4; nn++) {
        int col = ct4 * 32 + nn * 8 + tig * 2;
        *(float2*)&sEf[row0][col]     = make_float2(c[nn][0], c[nn][1]);
        *(float2*)&sEf[row0 + 8][col] = make_float2(c[nn][2], c[nn][3]);
        *(unsigned*)&Xh[row0][col]     = pkb(__float2bfloat16_rn(c[nn][0]), __float2bfloat16_rn(c[nn][1]));
        *(unsigned*)&Xh[row0 + 8][col] = pkb(__float2bfloat16_rn(c[nn][2]), __float2bfloat16_rn(c[nn][3]));
    }
    __syncthreads();

    // ---- coalesced edge_feat store + vector segment-sum (red.v4) ----
#pragma unroll
    for (int k = 0; k < 4; k++) {
        int e = warp + k * 8;
        int c4 = lane * 4;
        int ee = base + e;
        if (ee < EE) {
            float4 v = *(const float4*)&sEf[e][c4];
            *(float4*)&edge_out[(size_t)ee * Dc + c4] = v;
            red4(&g_agg[(size_t)sRow[e] * Dc + c4], v);
        }
    }

    // ---- coord MLP: cw = silu(ef@Wc1+bc1) @ Wc2 (hi-only A) ----
#pragma unroll
    for (int nn = 0; nn < 4; nn++)
#pragma unroll
        for (int j = 0; j < 4; j++) c[nn][j] = 0.f;
    gemm_pass4h(c, Xh, 24, rt, ct4, lane);

    {
        float pA = 0.f, pB = 0.f;
#pragma unroll
        for (int nn = 0; nn < 4; nn++) {
            int col = ct4 * 32 + nn * 8 + tig * 2;
            float2 bc = __ldg((const float2*)&bc1[col]);
            float2 w2 = __ldg((const float2*)&Wc2[col]);
            pA += siluf_(c[nn][0] + bc.x) * w2.x + siluf_(c[nn][1] + bc.y) * w2.y;
            pB += siluf_(c[nn][2] + bc.x) * w2.x + siluf_(c[nn][3] + bc.y) * w2.y;
        }
        pA += __shfl_xor_sync(0xffffffffu, pA, 1); pA += __shfl_xor_sync(0xffffffffu, pA, 2);
        pB += __shfl_xor_sync(0xffffffffu, pB, 1); pB += __shfl_xor_sync(0xffffffffu, pB, 2);
        if (tig == 0) { sPart[ct4][row0] = pA; sPart[ct4][row0 + 8] = pB; }
    }
    __syncthreads();
    if (ct4 == 0) {
#pragma unroll
        for (int half = 0; half < 2; half++) {
            int rr = row0 + half * 8;
            int ee = base + rr;
            if (ee < EE) {
                float cw = sPart[0][rr] + sPart[1][rr] + sPart[2][rr] + sPart[3][rr];
                if (tig < 3) {
                    float t = clampt_(sCd[rr][tig] * cw);
                    atomicAdd(&g_csum[(size_t)sRow[rr] * 3 + tig], t);
                } else {
                    atomicAdd(&g_deg[sRow[rr]], 1.f);
                }
            }
        }
    }
}

__global__ void __launch_bounds__(256) node_kernel(
    const float* __restrict__ h, const float* __restrict__ coord,
    const float* __restrict__ bn1, const float* __restrict__ bn2,
    float* __restrict__ hout, float* __restrict__ cout) {
    __shared__ __nv_bfloat16 Xh[TE][XPAD];
    __shared__ __nv_bfloat16 Xl[TE][XPAD];

    const int tid = threadIdx.x;
    const int lane = tid & 31;
    const int warp = tid >> 5;
    const int rt = warp >> 1;
    const int ct = warp & 1;
    const int g = lane >> 2;
    const int tig = lane & 3;
    const int row0 = rt * 16 + g;
    const int base = blockIdx.x * TE;

    float c[8][4];
#pragma unroll
    for (int nn = 0; nn < 8; nn++)
#pragma unroll
        for (int j = 0; j < 4; j++) c[nn][j] = 0.f;

    for (int i = tid; i < TE * 32; i += 256) {
        int n = base + (i >> 5);
        if (n >= NN) n = NN - 1;
        int l4 = (i & 31) * 4;
        float4 v = __ldg((const float4*)&h[(size_t)n * Dc + l4]);
        __nv_bfloat16 h0, l0, h1, l1, h2, l2, h3, l3;
        splitbf(v.x, h0, l0); splitbf(v.y, h1, l1); splitbf(v.z, h2, l2); splitbf(v.w, h3, l3);
        *(uint2*)&Xh[i >> 5][l4] = make_uint2(pkb(h0, h1), pkb(h2, h3));
        *(uint2*)&Xl[i >> 5][l4] = make_uint2(pkb(l0, l1), pkb(l2, l3));
    }
    __syncthreads();
    gemm_pass8(c, Xh, Xl, 32, rt, ct, lane);  // Wn1 rows [0,128): h part
    __syncthreads();

    for (int i = tid; i < TE * 32; i += 256) {
        int n = base + (i >> 5);
        if (n >= NN) n = NN - 1;
        int l4 = (i & 31) * 4;
        float4 v = *(const float4*)&g_agg[(size_t)n * Dc + l4];
        __nv_bfloat16 h0, l0, h1, l1, h2, l2, h3, l3;
        splitbf(v.x, h0, l0); splitbf(v.y, h1, l1); splitbf(v.z, h2, l2); splitbf(v.w, h3, l3);
        *(uint2*)&Xh[i >> 5][l4] = make_uint2(pkb(h0, h1), pkb(h2, h3));
        *(uint2*)&Xl[i >> 5][l4] = make_uint2(pkb(l0, l1), pkb(l2, l3));
    }
    __syncthreads();
    gemm_pass8(c, Xh, Xl, 40, rt, ct, lane);  // Wn1 rows [128,256): agg part
    __syncthreads();

#pragma unroll
    for (int nn = 0; nn < 8; nn++) {
        int col = ct * 64 + nn * 8 + tig * 2;
        float2 b1 = __ldg((const float2*)&bn1[col]);
        c[nn][0] = siluf_(c[nn][0] + b1.x);
        c[nn][1] = siluf_(c[nn][1] + b1.y);
        c[nn][2] = siluf_(c[nn][2] + b1.x);
        c[nn][3] = siluf_(c[nn][3] + b1.y);
        __nv_bfloat16 h0, l0, h1, l1, h2, l2, h3, l3;
        splitbf(c[nn][0], h0, l0); splitbf(c[nn][1], h1, l1);
        splitbf(c[nn][2], h2, l2); splitbf(c[nn][3], h3, l3);
        *(unsigned*)&Xh[row0][col]     = pkb(h0, h1);
        *(unsigned*)&Xh[row0 + 8][col] = pkb(h2, h3);
        *(unsigned*)&Xl[row0][col]     = pkb(l0, l1);
        *(unsigned*)&Xl[row0 + 8][col] = pkb(l2, l3);
    }
    __syncthreads();

#pragma unroll
    for (int nn = 0; nn < 8; nn++)
#pragma unroll
        for (int j = 0; j < 4; j++) c[nn][j] = 0.f;
    gemm_pass8(c, Xh, Xl, 48, rt, ct, lane);  // Wn2

    {
        int n0 = base + row0, n1 = base + row0 + 8;
#pragma unroll
        for (int nn = 0; nn < 8; nn++) {
            int col = ct * 64 + nn * 8 + tig * 2;
            float2 b2 = __ldg((const float2*)&bn2[col]);
            if (n0 < NN) {
                float2 hv = __ldg((const float2*)&h[(size_t)n0 * Dc + col]);
                *(float2*)&hout[(size_t)n0 * Dc + col] =
                    make_float2(hv.x + c[nn][0] + b2.x, hv.y + c[nn][1] + b2.y);
            }
            if (n1 < NN) {
                float2 hv = __ldg((const float2*)&h[(size_t)n1 * Dc + col]);
                *(float2*)&hout[(size_t)n1 * Dc + col] =
                    make_float2(hv.x + c[nn][2] + b2.x, hv.y + c[nn][3] + b2.y);
            }
        }
    }

    if (tid < TE * 3) {
        int e = tid / 3, cc = tid % 3;
        int n = base + e;
        if (n < NN) {
            float d = fmaxf(g_deg[n], 1.f);
            float v = clampt_(g_csum[(size_t)n * 3 + cc] / d);
            cout[(size_t)n * 3 + cc] = coord[(size_t)n * 3 + cc] + v;
        }
    }
}

extern "C" void kernel_launch(void* const* d_in, const int* in_sizes, int n_in,
                              void* d_out, int out_size) {
    const float* h     = (const float*)d_in[0];
    const int*   ei    = (const int*)d_in[1];   // jax x64 disabled -> int32
    const float* coord = (const float*)d_in[2];
    const float* We1   = (const float*)d_in[3];
    const float* be1   = (const float*)d_in[4];
    const float* We2   = (const float*)d_in[5];
    const float* be2   = (const float*)d_in[6];
    const float* Watt  = (const float*)d_in[7];
    const float* batt  = (const float*)d_in[8];
    const float* Wc1   = (const float*)d_in[9];
    const float* bc1   = (const float*)d_in[10];
    const float* Wc2   = (const float*)d_in[11];
    const float* Wn1   = (const float*)d_in[12];
    const float* bn1   = (const float*)d_in[13];
    const float* Wn2   = (const float*)d_in[14];
    const float* bn2   = (const float*)d_in[15];

    float* out  = (float*)d_out;
    float* hout = out;                                   // [N,128]
    float* cout = out + (size_t)NN * Dc;                 // [N,3]
    float* eout = cout + (size_t)NN * 3;                 // [E,128]

    zero_kernel<<<2048, 256>>>();
    prep_weights<<<(56 * 16 * 32 + 255) / 256, 256>>>(We1, We2, Wc1, Wn1, Wn2);
    pq_kernel<<<(NN + TE - 1) / TE, 256>>>(h);
    edge_kernel<<<(EE + TEE - 1) / TEE, 256>>>(ei, coord, We1, be1,
                                               be2, Watt, batt, bc1, Wc2, eout);
    node_kernel<<<(NN + TE - 1) / TE, 256>>>(h, coord, bn1, bn2, hout, cout);
}